// round 13
// baseline (speedup 1.0000x reference)
#include <cuda_runtime.h>
#include <math.h>

// Problem constants (fixed by the dataset)
#define NU 60000
#define NI 40000
#define NN 100000     // NU + NI
#define NE 500000
#define D  64
#define NF 4
#define NBLK 98       // ceil(NN/1024) for the scan
#define FULLM 0xFFFFFFFFu

// ---------------- static device scratch ----------------
__device__ float  g_ego0[NN * D];
__device__ float  g_ego1[NN * D];
__device__ float  g_all [NN * D];
__device__ float  g_tv0 [NN * D];    // tv double buffer
__device__ float  g_tv1 [NN * D];
__device__ float4 g_S4  [NE];        // raw S (written only on the final iteration)
__device__ float4 g_wsmA[2 * NE];    // slot-ordered enorm*softmax(S), double buffer
__device__ float4 g_wsmB[2 * NE];
__device__ float  g_dinv[NN];
__device__ int    g_deg [NN];
__device__ int    g_rowstart[NN + 1];
__device__ int    g_cnt [NN];
__device__ int    g_blocksum[NBLK];
__device__ float4 g_adj [2 * NE];    // {src, peer_slot, enorm, eid}

// ---------------- setup kernels ----------------

// fused: ego0 = concat(user,item); all = ego0; tv0 = tanh(l2norm_factor(ego0))
__global__ void k_init_tv(const float* __restrict__ u, const float* __restrict__ it) {
    int gw = (blockIdx.x * blockDim.x + threadIdx.x) >> 5;
    if (gw >= NN) return;
    int lane = threadIdx.x & 31;
    const float* srcp = (gw < NU) ? (u + (size_t)gw * D)
                                  : (it + (size_t)(gw - NU) * D);
    float2 a = reinterpret_cast<const float2*>(srcp)[lane];
    reinterpret_cast<float2*>(g_ego0 + (size_t)gw * D)[lane] = a;
    reinterpret_cast<float2*>(g_all  + (size_t)gw * D)[lane] = a;
    float ss = a.x * a.x + a.y * a.y;
    ss += __shfl_xor_sync(FULLM, ss, 1);
    ss += __shfl_xor_sync(FULLM, ss, 2);
    ss += __shfl_xor_sync(FULLM, ss, 4);
    float rinv = 1.0f / fmaxf(sqrtf(ss), 1e-12f);
    float2 o;
    o.x = tanhf(a.x * rinv);
    o.y = tanhf(a.y * rinv);
    reinterpret_cast<float2*>(g_tv0 + (size_t)gw * D)[lane] = o;
}

__global__ void k_deg(const int* __restrict__ ei) {
    int j = blockIdx.x * blockDim.x + threadIdx.x;
    if (j >= NE) return;
    atomicAdd(&g_deg[ei[j]], 1);
    atomicAdd(&g_deg[ei[NE + j]], 1);
}

// fused: dinv[n] = deg^-0.5 AND per-block partial sums of deg
__global__ void k_dinv_partial() {
    __shared__ int sh[1024];
    int t = threadIdx.x, n = blockIdx.x * 1024 + t;
    int d = (n < NN) ? g_deg[n] : 0;
    if (n < NN) g_dinv[n] = (d > 0) ? (1.0f / sqrtf((float)d)) : 0.0f;
    sh[t] = d;
    __syncthreads();
    for (int o = 512; o > 0; o >>= 1) {
        if (t < o) sh[t] += sh[t + o];
        __syncthreads();
    }
    if (t == 0) g_blocksum[blockIdx.x] = sh[0];
}

// parallel exclusive scan of NBLK block sums
__global__ void k_scanblocks() {
    __shared__ int wsum[4];
    int t = threadIdx.x;
    int v = (t < NBLK) ? g_blocksum[t] : 0;
    int x = v;
    for (int o = 1; o < 32; o <<= 1) {
        int y = __shfl_up_sync(FULLM, x, o);
        if ((t & 31) >= o) x += y;
    }
    if ((t & 31) == 31) wsum[t >> 5] = x;
    __syncthreads();
    if (t == 0) {
        int acc = 0;
        for (int i = 0; i < 4; i++) { int w = wsum[i]; wsum[i] = acc; acc += w; }
    }
    __syncthreads();
    int base = wsum[t >> 5];
    if (t < NBLK) g_blocksum[t] = base + x - v;
    if (t == 0) g_rowstart[NN] = 2 * NE;
}

__global__ void k_offsets() {
    __shared__ int sh[1024];
    int t = threadIdx.x, n = blockIdx.x * 1024 + t;
    int v = (n < NN) ? g_deg[n] : 0;
    sh[t] = v;
    __syncthreads();
    for (int o = 1; o < 1024; o <<= 1) {
        int x = (t >= o) ? sh[t - o] : 0;
        __syncthreads();
        sh[t] += x;
        __syncthreads();
    }
    if (n < NN) g_rowstart[n] = g_blocksum[blockIdx.x] + sh[t] - v;
}

// per-edge fill: both adjacency entries (with peer links) + both slot-ordered
// initial weight entries (enorm * softmax(S_in))
__global__ void k_fill_sm(const int* __restrict__ ei, const float* __restrict__ S) {
    int j = blockIdx.x * blockDim.x + threadIdx.x;
    if (j >= NE) return;
    int r = ei[j], c = ei[NE + j];
    int posF = g_rowstart[c] + atomicAdd(&g_cnt[c], 1);   // dst=c, src=r
    int posR = g_rowstart[r] + atomicAdd(&g_cnt[r], 1);   // dst=r, src=c
    float en = g_dinv[r] * g_dinv[c];
    g_adj[posF] = make_float4(__int_as_float(r), __int_as_float(posR), en,
                              __int_as_float(j));
    g_adj[posR] = make_float4(__int_as_float(c), __int_as_float(posF), en,
                              __int_as_float(j));
    float4 s = make_float4(S[j], S[NE + j], S[2 * NE + j], S[3 * NE + j]);
    float m  = fmaxf(fmaxf(s.x, s.y), fmaxf(s.z, s.w));
    float e0 = expf(s.x - m), e1 = expf(s.y - m);
    float e2 = expf(s.z - m), e3 = expf(s.w - m);
    float rr = 1.0f / (e0 + e1 + e2 + e3);
    float4 w = make_float4(en * e0 * rr, en * e1 * rr, en * e2 * rr, en * e3 * rr);
    g_wsmA[posF] = w;
    g_wsmA[posR] = w;
}

// broadcast source lane j's per-factor weight vector; return this lane's factor
__device__ __forceinline__ float bcast_w(float4 w4, int j, int kf) {
    float wx = __shfl_sync(FULLM, w4.x, j);
    float wy = __shfl_sync(FULLM, w4.y, j);
    float wz = __shfl_sync(FULLM, w4.z, j);
    float ww = __shfl_sync(FULLM, w4.w, j);
    return (kf == 0) ? wx : (kf == 1) ? wy : (kf == 2) ? wz : ww;
}

// conv over a batch of up to 32 adjacency entries (unroll x4, R10 sweet spot)
__device__ __forceinline__ void conv_batch(float2& acc, const float* __restrict__ ego,
                                           int src, float4 w4, int n, int lane, int kf) {
    int j = 0;
    for (; j + 4 <= n; j += 4) {
        int s0 = __shfl_sync(FULLM, src, j);
        int s1 = __shfl_sync(FULLM, src, j + 1);
        int s2 = __shfl_sync(FULLM, src, j + 2);
        int s3 = __shfl_sync(FULLM, src, j + 3);
        float2 v0 = *reinterpret_cast<const float2*>(ego + (size_t)s0 * D + lane * 2);
        float2 v1 = *reinterpret_cast<const float2*>(ego + (size_t)s1 * D + lane * 2);
        float2 v2 = *reinterpret_cast<const float2*>(ego + (size_t)s2 * D + lane * 2);
        float2 v3 = *reinterpret_cast<const float2*>(ego + (size_t)s3 * D + lane * 2);
        float w0 = bcast_w(w4, j,     kf);
        float w1 = bcast_w(w4, j + 1, kf);
        float w2 = bcast_w(w4, j + 2, kf);
        float w3 = bcast_w(w4, j + 3, kf);
        acc.x += w0 * v0.x; acc.y += w0 * v0.y;
        acc.x += w1 * v1.x; acc.y += w1 * v1.y;
        acc.x += w2 * v2.x; acc.y += w2 * v2.y;
        acc.x += w3 * v3.x; acc.y += w3 * v3.y;
    }
    for (; j < n; j++) {
        int sj = __shfl_sync(FULLM, src, j);
        float2 v = *reinterpret_cast<const float2*>(ego + (size_t)sj * D + lane * 2);
        float wj = bcast_w(w4, j, kf);
        acc.x += wj * v.x; acc.y += wj * v.y;
    }
}

// score over a batch (unroll x2, R10 sweet spot)
__device__ __forceinline__ float4 score_batch(float2 acc, const float* __restrict__ tv,
                                              int item, int n, int lane) {
    float4 pp = make_float4(0, 0, 0, 0);
    int j = 0;
    for (; j + 2 <= n; j += 2) {
        int i0 = __shfl_sync(FULLM, item, j);
        int i1 = __shfl_sync(FULLM, item, j + 1);
        float2 t0 = *reinterpret_cast<const float2*>(tv + (size_t)i0 * D + lane * 2);
        float2 t1 = *reinterpret_cast<const float2*>(tv + (size_t)i1 * D + lane * 2);
        float pa = acc.x * t0.x + acc.y * t0.y;
        float pb = acc.x * t1.x + acc.y * t1.y;
        pa += __shfl_xor_sync(FULLM, pa, 1);  pb += __shfl_xor_sync(FULLM, pb, 1);
        pa += __shfl_xor_sync(FULLM, pa, 2);  pb += __shfl_xor_sync(FULLM, pb, 2);
        pa += __shfl_xor_sync(FULLM, pa, 4);  pb += __shfl_xor_sync(FULLM, pb, 4);
        float qa0 = __shfl_sync(FULLM, pa, 0),  qa1 = __shfl_sync(FULLM, pa, 8);
        float qa2 = __shfl_sync(FULLM, pa, 16), qa3 = __shfl_sync(FULLM, pa, 24);
        float qb0 = __shfl_sync(FULLM, pb, 0),  qb1 = __shfl_sync(FULLM, pb, 8);
        float qb2 = __shfl_sync(FULLM, pb, 16), qb3 = __shfl_sync(FULLM, pb, 24);
        if (lane == j)     pp = make_float4(qa0, qa1, qa2, qa3);
        if (lane == j + 1) pp = make_float4(qb0, qb1, qb2, qb3);
    }
    for (; j < n; j++) {
        int ij = __shfl_sync(FULLM, item, j);
        float2 t = *reinterpret_cast<const float2*>(tv + (size_t)ij * D + lane * 2);
        float p = acc.x * t.x + acc.y * t.y;
        p += __shfl_xor_sync(FULLM, p, 1);
        p += __shfl_xor_sync(FULLM, p, 2);
        p += __shfl_xor_sync(FULLM, p, 4);
        float q0 = __shfl_sync(FULLM, p, 0),  q1 = __shfl_sync(FULLM, p, 8);
        float q2 = __shfl_sync(FULLM, p, 16), q3 = __shfl_sync(FULLM, p, 24);
        if (lane == j) pp = make_float4(q0, q1, q2, q3);
    }
    return pp;
}

// ---------------- fused conv + score + softmax, one warp per node ----------------
// Conv reads TWO coalesced sequential streams (adj, wsm_in) — no gathers except
// ego rows. Score writes next weights to own slot (coalesced) + peer slot
// (scattered store, fire-and-forget). Dead stores eliminated:
//   it=0: xn never read -> not written.  FINAL: xn/tv_next never read -> not
//   written; output embeddings written directly (g_all + acc).
template <bool LASTIT, bool FINAL>
__global__ void __launch_bounds__(256)
k_fused(const float* __restrict__ ego, float* __restrict__ xn,
        const float* __restrict__ tv, float* __restrict__ tv_next,
        const float4* __restrict__ wsm_in, float4* __restrict__ wsm_out,
        float* __restrict__ outEmb) {
    int gw = (blockIdx.x * blockDim.x + threadIdx.x) >> 5;
    if (gw >= NN) return;
    int lane = threadIdx.x & 31;
    int kf = lane >> 3;
    int s = g_rowstart[gw], e = g_rowstart[gw + 1];
    int deg = e - s;

    // ---- phase 1: conv ----
    float2 acc = make_float2(0.0f, 0.0f);
    int c_src = 0, c_eid = 0, c_peer = 0;
    float c_en = 0.0f;
    float4 c_w4 = make_float4(0, 0, 0, 0);
    for (int b = s; b < e; b += 32) {
        int n = min(32, e - b);
        int src = 0;
        float4 w4 = make_float4(0, 0, 0, 0);
        if (lane < n) {
            float4 a = g_adj[b + lane];       // coalesced stream
            w4 = wsm_in[b + lane];            // coalesced stream (independent)
            src = __float_as_int(a.x);
            c_src = src; c_peer = __float_as_int(a.y);
            c_en = a.z;  c_eid = __float_as_int(a.w);
            c_w4 = w4;                        // carry (valid whole list if deg<=32)
        }
        conv_batch(acc, ego, src, w4, n, lane, kf);
    }

    // per-factor inverse norm
    float ss = acc.x * acc.x + acc.y * acc.y;
    ss += __shfl_xor_sync(FULLM, ss, 1);
    ss += __shfl_xor_sync(FULLM, ss, 2);
    ss += __shfl_xor_sync(FULLM, ss, 4);
    float rinv = 1.0f / fmaxf(sqrtf(ss), 1e-12f);

    if (FINAL) {
        // output embeddings directly: out = all_embs + x_new
        float2 av = reinterpret_cast<const float2*>(g_all + (size_t)gw * D)[lane];
        av.x += acc.x; av.y += acc.y;
        reinterpret_cast<float2*>(outEmb + (size_t)gw * D)[lane] = av;
    } else if (LASTIT) {
        reinterpret_cast<float2*>(xn + (size_t)gw * D)[lane] = acc;  // next ego
        float2* ap = reinterpret_cast<float2*>(g_all + (size_t)gw * D) + lane;
        float2 av = *ap;
        av.x += acc.x; av.y += acc.y;
        *ap = av;
        float2 t;
        t.x = tanhf(acc.x * rinv);
        t.y = tanhf(acc.y * rinv);
        reinterpret_cast<float2*>(tv_next + (size_t)gw * D)[lane] = t;
    }
    // it=0: x_new is never read -> no stores

    // ---- phase 2: score (user nodes only) ----
    if (gw >= NU) return;

    float r0 = __shfl_sync(FULLM, rinv, 0);
    float r1 = __shfl_sync(FULLM, rinv, 8);
    float r2 = __shfl_sync(FULLM, rinv, 16);
    float r3 = __shfl_sync(FULLM, rinv, 24);

    if (deg <= 32) {
        float4 pp = score_batch(acc, tv, c_src, deg, lane);
        if (lane < deg) {
            float eni = 1.0f / c_en;                         // en>0 on real edges
            float4 sv = make_float4(c_w4.x * eni + pp.x * r0,
                                    c_w4.y * eni + pp.y * r1,
                                    c_w4.z * eni + pp.z * r2,
                                    c_w4.w * eni + pp.w * r3);
            if (FINAL) {
                g_S4[c_eid] = sv;
            } else {
                float m  = fmaxf(fmaxf(sv.x, sv.y), fmaxf(sv.z, sv.w));
                float e0 = expf(sv.x - m), e1 = expf(sv.y - m);
                float e2 = expf(sv.z - m), e3 = expf(sv.w - m);
                float rr = c_en / (e0 + e1 + e2 + e3);
                float4 wn = make_float4(e0 * rr, e1 * rr, e2 * rr, e3 * rr);
                wsm_out[s + lane] = wn;          // own slot: coalesced
                wsm_out[c_peer]  = wn;           // peer slot: scattered store
            }
        }
    } else {
        for (int b = s; b < e; b += 32) {
            int n = min(32, e - b);
            int item = 0, eid = 0, peer = 0;
            float en = 0.0f;
            float4 w4 = make_float4(0, 0, 0, 0);
            if (lane < n) {
                float4 a = g_adj[b + lane];
                w4 = wsm_in[b + lane];
                item = __float_as_int(a.x);
                peer = __float_as_int(a.y);
                en   = a.z;
                eid  = __float_as_int(a.w);
            }
            float4 pp = score_batch(acc, tv, item, n, lane);
            if (lane < n) {
                float eni = 1.0f / en;
                float4 sv = make_float4(w4.x * eni + pp.x * r0,
                                        w4.y * eni + pp.y * r1,
                                        w4.z * eni + pp.z * r2,
                                        w4.w * eni + pp.w * r3);
                if (FINAL) {
                    g_S4[eid] = sv;
                } else {
                    float m  = fmaxf(fmaxf(sv.x, sv.y), fmaxf(sv.z, sv.w));
                    float e0 = expf(sv.x - m), e1 = expf(sv.y - m);
                    float e2 = expf(sv.z - m), e3 = expf(sv.w - m);
                    float rr = en / (e0 + e1 + e2 + e3);
                    float4 wn = make_float4(e0 * rr, e1 * rr, e2 * rr, e3 * rr);
                    wsm_out[b + lane] = wn;
                    wsm_out[peer]    = wn;
                }
            }
        }
    }
}

// output S transpose [NE,4] -> [4,NE]
__global__ void k_transS_out(float* __restrict__ outS) {
    int j = blockIdx.x * blockDim.x + threadIdx.x;
    if (j >= NE) return;
    float4 s = g_S4[j];
    outS[j]          = s.x;
    outS[NE + j]     = s.y;
    outS[2 * NE + j] = s.z;
    outS[3 * NE + j] = s.w;
}

// ---------------- host orchestration ----------------

extern "C" void kernel_launch(void* const* d_in, const int* in_sizes, int n_in,
                              void* d_out, int out_size) {
    const float* user = (const float*)d_in[0];
    const float* item = (const float*)d_in[1];
    const float* Sin  = (const float*)d_in[2];
    const int*   ei   = (const int*)d_in[3];
    float* out = (float*)d_out;

    void *p_deg, *p_cnt, *p_ego0, *p_ego1, *p_tv0, *p_tv1, *p_wsmA, *p_wsmB;
    cudaGetSymbolAddress(&p_deg,  g_deg);
    cudaGetSymbolAddress(&p_cnt,  g_cnt);
    cudaGetSymbolAddress(&p_ego0, g_ego0);
    cudaGetSymbolAddress(&p_ego1, g_ego1);
    cudaGetSymbolAddress(&p_tv0,  g_tv0);
    cudaGetSymbolAddress(&p_tv1,  g_tv1);
    cudaGetSymbolAddress(&p_wsmA, g_wsmA);
    cudaGetSymbolAddress(&p_wsmB, g_wsmB);

    const int T = 256;
    const int gEdge  = (NE + T - 1) / T;
    const int gNodeW = (NN * 32 + T - 1) / T;

    // ---- setup ----
    cudaMemsetAsync(p_deg, 0, NN * sizeof(int), 0);
    cudaMemsetAsync(p_cnt, 0, NN * sizeof(int), 0);
    k_init_tv<<<gNodeW, T>>>(user, item);
    k_deg<<<gEdge, T>>>(ei);
    k_dinv_partial<<<NBLK, 1024>>>();
    k_scanblocks<<<1, 128>>>();
    k_offsets<<<NBLK, 1024>>>();
    k_fill_sm<<<gEdge, T>>>(ei, Sin);

    // ---- 2 layers x 2 routing iterations, 1 fused kernel each ----
    float*  ego  = (float*)p_ego0;
    float*  xn   = (float*)p_ego1;
    float*  tv   = (float*)p_tv0;
    float*  tvn  = (float*)p_tv1;
    float4* wA   = (float4*)p_wsmA;
    float4* wB   = (float4*)p_wsmB;

    // layer 0
    k_fused<false, false><<<gNodeW, T>>>(ego, xn, tv, tvn, wA, wB, out);
    { float4* t = wA; wA = wB; wB = t; }
    k_fused<true,  false><<<gNodeW, T>>>(ego, xn, tv, tvn, wA, wB, out);
    { float4* t = wA; wA = wB; wB = t; }
    { float* t = ego; ego = xn; xn = t; t = tv; tv = tvn; tvn = t; }
    // layer 1
    k_fused<false, false><<<gNodeW, T>>>(ego, xn, tv, tvn, wA, wB, out);
    { float4* t = wA; wA = wB; wB = t; }
    k_fused<true,  true ><<<gNodeW, T>>>(ego, xn, tv, tvn, wA, wB, out);

    // ---- output S: [4, NE] after the embeddings ----
    k_transS_out<<<gEdge, T>>>(out + (size_t)NN * D);
}

// round 14
// speedup vs baseline: 1.0918x; 1.0918x over previous
#include <cuda_runtime.h>
#include <math.h>

// Problem constants (fixed by the dataset)
#define NU 60000
#define NI 40000
#define NN 100000     // NU + NI
#define NE 500000
#define D  64
#define NF 4
#define NBLK 98       // ceil(NN/1024) for the scan
#define FULLM 0xFFFFFFFFu

// ---------------- static device scratch ----------------
__device__ float  g_ego0[NN * D];
__device__ float  g_ego1[NN * D];
__device__ float  g_all [NN * D];
__device__ float  g_tv0 [NN * D];    // tv double buffer
__device__ float  g_tv1 [NN * D];
__device__ float4 g_S4  [NE];        // raw S (written only on the final iteration)
__device__ float4 g_SsmA[NE];        // softmax(S) double buffer
__device__ float4 g_SsmB[NE];
__device__ float  g_dinv[NN];
__device__ int    g_deg [NN];
__device__ int    g_rowstart[NN + 1];
__device__ int    g_cnt [NN];
__device__ int    g_blocksum[NBLK];
__device__ float4 g_adj [2 * NE];    // {src, eid, enorm, unused}

// ---------------- setup kernels ----------------

// fused: ego0 = concat(user,item); all = ego0; tv0 = tanh(l2norm_factor(ego0))
__global__ void k_init_tv(const float* __restrict__ u, const float* __restrict__ it) {
    int gw = (blockIdx.x * blockDim.x + threadIdx.x) >> 5;
    if (gw >= NN) return;
    int lane = threadIdx.x & 31;
    const float* srcp = (gw < NU) ? (u + (size_t)gw * D)
                                  : (it + (size_t)(gw - NU) * D);
    float2 a = reinterpret_cast<const float2*>(srcp)[lane];
    reinterpret_cast<float2*>(g_ego0 + (size_t)gw * D)[lane] = a;
    reinterpret_cast<float2*>(g_all  + (size_t)gw * D)[lane] = a;
    float ss = a.x * a.x + a.y * a.y;
    ss += __shfl_xor_sync(FULLM, ss, 1);
    ss += __shfl_xor_sync(FULLM, ss, 2);
    ss += __shfl_xor_sync(FULLM, ss, 4);
    float rinv = 1.0f / fmaxf(sqrtf(ss), 1e-12f);
    float2 o;
    o.x = tanhf(a.x * rinv);
    o.y = tanhf(a.y * rinv);
    reinterpret_cast<float2*>(g_tv0 + (size_t)gw * D)[lane] = o;
}

__global__ void k_deg(const int* __restrict__ ei) {
    int j = blockIdx.x * blockDim.x + threadIdx.x;
    if (j >= NE) return;
    atomicAdd(&g_deg[ei[j]], 1);
    atomicAdd(&g_deg[ei[NE + j]], 1);
}

// fused: dinv[n] = deg^-0.5 AND per-block partial sums of deg
__global__ void k_dinv_partial() {
    __shared__ int sh[1024];
    int t = threadIdx.x, n = blockIdx.x * 1024 + t;
    int d = (n < NN) ? g_deg[n] : 0;
    if (n < NN) g_dinv[n] = (d > 0) ? (1.0f / sqrtf((float)d)) : 0.0f;
    sh[t] = d;
    __syncthreads();
    for (int o = 512; o > 0; o >>= 1) {
        if (t < o) sh[t] += sh[t + o];
        __syncthreads();
    }
    if (t == 0) g_blocksum[blockIdx.x] = sh[0];
}

// parallel exclusive scan of NBLK block sums
__global__ void k_scanblocks() {
    __shared__ int wsum[4];
    int t = threadIdx.x;
    int v = (t < NBLK) ? g_blocksum[t] : 0;
    int x = v;
    for (int o = 1; o < 32; o <<= 1) {
        int y = __shfl_up_sync(FULLM, x, o);
        if ((t & 31) >= o) x += y;
    }
    if ((t & 31) == 31) wsum[t >> 5] = x;
    __syncthreads();
    if (t == 0) {
        int acc = 0;
        for (int i = 0; i < 4; i++) { int w = wsum[i]; wsum[i] = acc; acc += w; }
    }
    __syncthreads();
    int base = wsum[t >> 5];
    if (t < NBLK) g_blocksum[t] = base + x - v;
    if (t == 0) g_rowstart[NN] = 2 * NE;
}

__global__ void k_offsets() {
    __shared__ int sh[1024];
    int t = threadIdx.x, n = blockIdx.x * 1024 + t;
    int v = (n < NN) ? g_deg[n] : 0;
    sh[t] = v;
    __syncthreads();
    for (int o = 1; o < 1024; o <<= 1) {
        int x = (t >= o) ? sh[t - o] : 0;
        __syncthreads();
        sh[t] += x;
        __syncthreads();
    }
    if (n < NN) g_rowstart[n] = g_blocksum[blockIdx.x] + sh[t] - v;
}

// fill CSR adjacency (both directions); forward thread also computes the
// initial softmax of the input S -> SsmA
__global__ void k_fill_sm(const int* __restrict__ ei, const float* __restrict__ S) {
    int d = blockIdx.x * blockDim.x + threadIdx.x;
    if (d >= 2 * NE) return;
    int j = (d < NE) ? d : d - NE;
    int r = ei[j], c = ei[NE + j];
    int src = (d < NE) ? r : c;
    int dst = (d < NE) ? c : r;
    int pos = g_rowstart[dst] + atomicAdd(&g_cnt[dst], 1);
    g_adj[pos] = make_float4(__int_as_float(src), __int_as_float(j),
                             g_dinv[src] * g_dinv[dst], 0.0f);
    if (d < NE) {
        float4 s = make_float4(S[j], S[NE + j], S[2 * NE + j], S[3 * NE + j]);
        float m  = fmaxf(fmaxf(s.x, s.y), fmaxf(s.z, s.w));
        float e0 = expf(s.x - m), e1 = expf(s.y - m);
        float e2 = expf(s.z - m), e3 = expf(s.w - m);
        float rr = 1.0f / (e0 + e1 + e2 + e3);
        g_SsmA[j] = make_float4(e0 * rr, e1 * rr, e2 * rr, e3 * rr);
    }
}

// broadcast source lane j's per-factor weight vector; return this lane's factor
__device__ __forceinline__ float bcast_w(float4 w4, int j, int kf) {
    float wx = __shfl_sync(FULLM, w4.x, j);
    float wy = __shfl_sync(FULLM, w4.y, j);
    float wz = __shfl_sync(FULLM, w4.z, j);
    float ww = __shfl_sync(FULLM, w4.w, j);
    return (kf == 0) ? wx : (kf == 1) ? wy : (kf == 2) ? wz : ww;
}

// conv over a batch of up to 32 adjacency entries (unroll x4, measured sweet spot)
__device__ __forceinline__ void conv_batch(float2& acc, const float* __restrict__ ego,
                                           int src, float4 w4, int n, int lane, int kf) {
    int j = 0;
    for (; j + 4 <= n; j += 4) {
        int s0 = __shfl_sync(FULLM, src, j);
        int s1 = __shfl_sync(FULLM, src, j + 1);
        int s2 = __shfl_sync(FULLM, src, j + 2);
        int s3 = __shfl_sync(FULLM, src, j + 3);
        float2 v0 = *reinterpret_cast<const float2*>(ego + (size_t)s0 * D + lane * 2);
        float2 v1 = *reinterpret_cast<const float2*>(ego + (size_t)s1 * D + lane * 2);
        float2 v2 = *reinterpret_cast<const float2*>(ego + (size_t)s2 * D + lane * 2);
        float2 v3 = *reinterpret_cast<const float2*>(ego + (size_t)s3 * D + lane * 2);
        float w0 = bcast_w(w4, j,     kf);
        float w1 = bcast_w(w4, j + 1, kf);
        float w2 = bcast_w(w4, j + 2, kf);
        float w3 = bcast_w(w4, j + 3, kf);
        acc.x += w0 * v0.x; acc.y += w0 * v0.y;
        acc.x += w1 * v1.x; acc.y += w1 * v1.y;
        acc.x += w2 * v2.x; acc.y += w2 * v2.y;
        acc.x += w3 * v3.x; acc.y += w3 * v3.y;
    }
    for (; j < n; j++) {
        int sj = __shfl_sync(FULLM, src, j);
        float2 v = *reinterpret_cast<const float2*>(ego + (size_t)sj * D + lane * 2);
        float wj = bcast_w(w4, j, kf);
        acc.x += wj * v.x; acc.y += wj * v.y;
    }
}

// score over a batch (unroll x2, measured sweet spot)
__device__ __forceinline__ float4 score_batch(float2 acc, const float* __restrict__ tv,
                                              int item, int n, int lane) {
    float4 pp = make_float4(0, 0, 0, 0);
    int j = 0;
    for (; j + 2 <= n; j += 2) {
        int i0 = __shfl_sync(FULLM, item, j);
        int i1 = __shfl_sync(FULLM, item, j + 1);
        float2 t0 = *reinterpret_cast<const float2*>(tv + (size_t)i0 * D + lane * 2);
        float2 t1 = *reinterpret_cast<const float2*>(tv + (size_t)i1 * D + lane * 2);
        float pa = acc.x * t0.x + acc.y * t0.y;
        float pb = acc.x * t1.x + acc.y * t1.y;
        pa += __shfl_xor_sync(FULLM, pa, 1);  pb += __shfl_xor_sync(FULLM, pb, 1);
        pa += __shfl_xor_sync(FULLM, pa, 2);  pb += __shfl_xor_sync(FULLM, pb, 2);
        pa += __shfl_xor_sync(FULLM, pa, 4);  pb += __shfl_xor_sync(FULLM, pb, 4);
        float qa0 = __shfl_sync(FULLM, pa, 0),  qa1 = __shfl_sync(FULLM, pa, 8);
        float qa2 = __shfl_sync(FULLM, pa, 16), qa3 = __shfl_sync(FULLM, pa, 24);
        float qb0 = __shfl_sync(FULLM, pb, 0),  qb1 = __shfl_sync(FULLM, pb, 8);
        float qb2 = __shfl_sync(FULLM, pb, 16), qb3 = __shfl_sync(FULLM, pb, 24);
        if (lane == j)     pp = make_float4(qa0, qa1, qa2, qa3);
        if (lane == j + 1) pp = make_float4(qb0, qb1, qb2, qb3);
    }
    for (; j < n; j++) {
        int ij = __shfl_sync(FULLM, item, j);
        float2 t = *reinterpret_cast<const float2*>(tv + (size_t)ij * D + lane * 2);
        float p = acc.x * t.x + acc.y * t.y;
        p += __shfl_xor_sync(FULLM, p, 1);
        p += __shfl_xor_sync(FULLM, p, 2);
        p += __shfl_xor_sync(FULLM, p, 4);
        float q0 = __shfl_sync(FULLM, p, 0),  q1 = __shfl_sync(FULLM, p, 8);
        float q2 = __shfl_sync(FULLM, p, 16), q3 = __shfl_sync(FULLM, p, 24);
        if (lane == j) pp = make_float4(q0, q1, q2, q3);
    }
    return pp;
}

// ---------------- fused conv + score + softmax, one warp per node ----------------
// R12 structure (Ssm gather in conv, register carry) + dead-store elimination:
//   it=0 (non-LASTIT): x_new is never read -> no row write.
//   FINAL: out = g_all + acc written directly; xn/tv_next/g_all stores skipped.
template <bool LASTIT, bool FINAL>
__global__ void __launch_bounds__(256)
k_fused(const float* __restrict__ ego, float* __restrict__ xn,
        const float* __restrict__ tv, float* __restrict__ tv_next,
        const float4* __restrict__ ssm_in, float4* __restrict__ ssm_out,
        float* __restrict__ outEmb) {
    int gw = (blockIdx.x * blockDim.x + threadIdx.x) >> 5;
    if (gw >= NN) return;
    int lane = threadIdx.x & 31;
    int kf = lane >> 3;
    int s = g_rowstart[gw], e = g_rowstart[gw + 1];
    int deg = e - s;

    // ---- phase 1: conv (batch loop + carry registers) ----
    float2 acc = make_float2(0.0f, 0.0f);
    int c_src = 0, c_eid = 0;
    float4 c_sm = make_float4(0, 0, 0, 0);
    for (int b = s; b < e; b += 32) {
        int n = min(32, e - b);
        int src = 0;
        float4 w4 = make_float4(0, 0, 0, 0);
        if (lane < n) {
            float4 a = g_adj[b + lane];                 // coalesced batch load
            src = __float_as_int(a.x);
            float4 sm = ssm_in[__float_as_int(a.y)];    // 32 gathers in flight
            w4 = make_float4(sm.x * a.z, sm.y * a.z, sm.z * a.z, sm.w * a.z);
            c_src = src; c_eid = __float_as_int(a.y); c_sm = sm;   // carry
        }
        conv_batch(acc, ego, src, w4, n, lane, kf);
    }

    // per-factor inverse norm (every lane ends with its 8-lane group's value)
    float ss = acc.x * acc.x + acc.y * acc.y;
    ss += __shfl_xor_sync(FULLM, ss, 1);
    ss += __shfl_xor_sync(FULLM, ss, 2);
    ss += __shfl_xor_sync(FULLM, ss, 4);
    float rinv = 1.0f / fmaxf(sqrtf(ss), 1e-12f);

    if (FINAL) {
        // out = all_embs + x_new, written once, directly to d_out
        float2 av = reinterpret_cast<const float2*>(g_all + (size_t)gw * D)[lane];
        av.x += acc.x; av.y += acc.y;
        reinterpret_cast<float2*>(outEmb + (size_t)gw * D)[lane] = av;
    } else if (LASTIT) {
        reinterpret_cast<float2*>(xn + (size_t)gw * D)[lane] = acc;  // next layer's ego
        float2* ap = reinterpret_cast<float2*>(g_all + (size_t)gw * D) + lane;
        float2 av = *ap;
        av.x += acc.x; av.y += acc.y;
        *ap = av;
        float2 t;
        t.x = tanhf(acc.x * rinv);
        t.y = tanhf(acc.y * rinv);
        reinterpret_cast<float2*>(tv_next + (size_t)gw * D)[lane] = t;
    }
    // it=0: x_new never read -> no stores

    // ---- phase 2: score (user nodes only) ----
    if (gw >= NU) return;

    float r0 = __shfl_sync(FULLM, rinv, 0);
    float r1 = __shfl_sync(FULLM, rinv, 8);
    float r2 = __shfl_sync(FULLM, rinv, 16);
    float r3 = __shfl_sync(FULLM, rinv, 24);

    if (deg <= 32) {
        // reuse carried registers: c_src (=item), c_eid, c_sm (=raw ssm_in[eid])
        float4 pp = score_batch(acc, tv, c_src, deg, lane);
        if (lane < deg) {
            float4 sv = make_float4(c_sm.x + pp.x * r0, c_sm.y + pp.y * r1,
                                    c_sm.z + pp.z * r2, c_sm.w + pp.w * r3);
            if (FINAL) {
                g_S4[c_eid] = sv;
            } else {
                float m  = fmaxf(fmaxf(sv.x, sv.y), fmaxf(sv.z, sv.w));
                float e0 = expf(sv.x - m), e1 = expf(sv.y - m);
                float e2 = expf(sv.z - m), e3 = expf(sv.w - m);
                float rr = 1.0f / (e0 + e1 + e2 + e3);
                ssm_out[c_eid] = make_float4(e0 * rr, e1 * rr, e2 * rr, e3 * rr);
            }
        }
    } else {
        for (int b = s; b < e; b += 32) {
            int n = min(32, e - b);
            int item = 0, eid = 0;
            float4 svr = make_float4(0, 0, 0, 0);
            if (lane < n) {
                float4 a = g_adj[b + lane];
                item = __float_as_int(a.x);
                eid  = __float_as_int(a.y);
                svr  = ssm_in[eid];
            }
            float4 pp = score_batch(acc, tv, item, n, lane);
            if (lane < n) {
                float4 sv = make_float4(svr.x + pp.x * r0, svr.y + pp.y * r1,
                                        svr.z + pp.z * r2, svr.w + pp.w * r3);
                if (FINAL) {
                    g_S4[eid] = sv;
                } else {
                    float m  = fmaxf(fmaxf(sv.x, sv.y), fmaxf(sv.z, sv.w));
                    float e0 = expf(sv.x - m), e1 = expf(sv.y - m);
                    float e2 = expf(sv.z - m), e3 = expf(sv.w - m);
                    float rr = 1.0f / (e0 + e1 + e2 + e3);
                    ssm_out[eid] = make_float4(e0 * rr, e1 * rr, e2 * rr, e3 * rr);
                }
            }
        }
    }
}

// output S transpose [NE,4] -> [4,NE]
__global__ void k_transS_out(float* __restrict__ outS) {
    int j = blockIdx.x * blockDim.x + threadIdx.x;
    if (j >= NE) return;
    float4 s = g_S4[j];
    outS[j]          = s.x;
    outS[NE + j]     = s.y;
    outS[2 * NE + j] = s.z;
    outS[3 * NE + j] = s.w;
}

// ---------------- host orchestration ----------------

extern "C" void kernel_launch(void* const* d_in, const int* in_sizes, int n_in,
                              void* d_out, int out_size) {
    const float* user = (const float*)d_in[0];
    const float* item = (const float*)d_in[1];
    const float* Sin  = (const float*)d_in[2];
    const int*   ei   = (const int*)d_in[3];
    float* out = (float*)d_out;

    void *p_deg, *p_cnt, *p_ego0, *p_ego1, *p_tv0, *p_tv1, *p_ssmA, *p_ssmB;
    cudaGetSymbolAddress(&p_deg,  g_deg);
    cudaGetSymbolAddress(&p_cnt,  g_cnt);
    cudaGetSymbolAddress(&p_ego0, g_ego0);
    cudaGetSymbolAddress(&p_ego1, g_ego1);
    cudaGetSymbolAddress(&p_tv0,  g_tv0);
    cudaGetSymbolAddress(&p_tv1,  g_tv1);
    cudaGetSymbolAddress(&p_ssmA, g_SsmA);
    cudaGetSymbolAddress(&p_ssmB, g_SsmB);

    const int T = 256;
    const int gEdge  = (NE + T - 1) / T;
    const int gDir   = (2 * NE + T - 1) / T;
    const int gNodeW = (NN * 32 + T - 1) / T;

    // ---- setup (6 kernels + 2 memsets) ----
    cudaMemsetAsync(p_deg, 0, NN * sizeof(int), 0);
    cudaMemsetAsync(p_cnt, 0, NN * sizeof(int), 0);
    k_init_tv<<<gNodeW, T>>>(user, item);
    k_deg<<<gEdge, T>>>(ei);
    k_dinv_partial<<<NBLK, 1024>>>();
    k_scanblocks<<<1, 128>>>();
    k_offsets<<<NBLK, 1024>>>();
    k_fill_sm<<<gDir, T>>>(ei, Sin);

    // ---- 2 layers x 2 routing iterations, 1 fused kernel each ----
    float*  ego  = (float*)p_ego0;
    float*  xn   = (float*)p_ego1;
    float*  tv   = (float*)p_tv0;
    float*  tvn  = (float*)p_tv1;
    float4* ssmA = (float4*)p_ssmA;
    float4* ssmB = (float4*)p_ssmB;

    // layer 0
    k_fused<false, false><<<gNodeW, T>>>(ego, xn, tv, tvn, ssmA, ssmB, out);
    { float4* t = ssmA; ssmA = ssmB; ssmB = t; }
    k_fused<true,  false><<<gNodeW, T>>>(ego, xn, tv, tvn, ssmA, ssmB, out);
    { float4* t = ssmA; ssmA = ssmB; ssmB = t; }
    { float* t = ego; ego = xn; xn = t; t = tv; tv = tvn; tvn = t; }
    // layer 1
    k_fused<false, false><<<gNodeW, T>>>(ego, xn, tv, tvn, ssmA, ssmB, out);
    { float4* t = ssmA; ssmA = ssmB; ssmB = t; }
    k_fused<true,  true ><<<gNodeW, T>>>(ego, xn, tv, tvn, ssmA, ssmB, out);

    // ---- output S: [4, NE] after the embeddings ----
    k_transS_out<<<gEdge, T>>>(out + (size_t)NN * D);
}

// round 15
// speedup vs baseline: 1.3116x; 1.2013x over previous
#include <cuda_runtime.h>
#include <math.h>

// Problem constants (fixed by the dataset)
#define NU 60000
#define NI 40000
#define NN 100000     // NU + NI
#define NE 500000
#define D  64
#define NF 4
#define NBLK 98       // ceil(NN/1024) for the scan
#define FULLM 0xFFFFFFFFu

// ---------------- static device scratch ----------------
__device__ float  g_ego0[NN * D];
__device__ float  g_ego1[NN * D];
__device__ float  g_all [NN * D];
__device__ float  g_tv0 [NN * D];    // tv double buffer
__device__ float  g_tv1 [NN * D];
__device__ float4 g_S4  [NE];        // raw S (written only on the final iteration)
__device__ float4 g_SsmA[NE];        // softmax(S) double buffer
__device__ float4 g_SsmB[NE];
__device__ float  g_dinv[NN];
__device__ int    g_deg [NN];
__device__ int    g_rowstart[NN + 1];
__device__ int    g_cnt [NN];
__device__ int    g_blocksum[NBLK];
__device__ float4 g_adj [2 * NE];    // {src, eid, enorm, unused}

// ---------------- setup kernels ----------------

// fused: ego0 = concat(user,item); all = ego0; tv0 = tanh(l2norm_factor(ego0))
__global__ void k_init_tv(const float* __restrict__ u, const float* __restrict__ it) {
    int gw = (blockIdx.x * blockDim.x + threadIdx.x) >> 5;
    if (gw >= NN) return;
    int lane = threadIdx.x & 31;
    const float* srcp = (gw < NU) ? (u + (size_t)gw * D)
                                  : (it + (size_t)(gw - NU) * D);
    float2 a = reinterpret_cast<const float2*>(srcp)[lane];
    reinterpret_cast<float2*>(g_ego0 + (size_t)gw * D)[lane] = a;
    reinterpret_cast<float2*>(g_all  + (size_t)gw * D)[lane] = a;
    float ss = a.x * a.x + a.y * a.y;
    ss += __shfl_xor_sync(FULLM, ss, 1);
    ss += __shfl_xor_sync(FULLM, ss, 2);
    ss += __shfl_xor_sync(FULLM, ss, 4);
    float rinv = 1.0f / fmaxf(sqrtf(ss), 1e-12f);
    float2 o;
    o.x = tanhf(a.x * rinv);
    o.y = tanhf(a.y * rinv);
    reinterpret_cast<float2*>(g_tv0 + (size_t)gw * D)[lane] = o;
}

__global__ void k_deg(const int* __restrict__ ei) {
    int j = blockIdx.x * blockDim.x + threadIdx.x;
    if (j >= NE) return;
    atomicAdd(&g_deg[ei[j]], 1);
    atomicAdd(&g_deg[ei[NE + j]], 1);
}

// fused: dinv[n] = deg^-0.5 AND per-block partial sums of deg
__global__ void k_dinv_partial() {
    __shared__ int sh[1024];
    int t = threadIdx.x, n = blockIdx.x * 1024 + t;
    int d = (n < NN) ? g_deg[n] : 0;
    if (n < NN) g_dinv[n] = (d > 0) ? (1.0f / sqrtf((float)d)) : 0.0f;
    sh[t] = d;
    __syncthreads();
    for (int o = 512; o > 0; o >>= 1) {
        if (t < o) sh[t] += sh[t + o];
        __syncthreads();
    }
    if (t == 0) g_blocksum[blockIdx.x] = sh[0];
}

// parallel exclusive scan of NBLK block sums
__global__ void k_scanblocks() {
    __shared__ int wsum[4];
    int t = threadIdx.x;
    int v = (t < NBLK) ? g_blocksum[t] : 0;
    int x = v;
    for (int o = 1; o < 32; o <<= 1) {
        int y = __shfl_up_sync(FULLM, x, o);
        if ((t & 31) >= o) x += y;
    }
    if ((t & 31) == 31) wsum[t >> 5] = x;
    __syncthreads();
    if (t == 0) {
        int acc = 0;
        for (int i = 0; i < 4; i++) { int w = wsum[i]; wsum[i] = acc; acc += w; }
    }
    __syncthreads();
    int base = wsum[t >> 5];
    if (t < NBLK) g_blocksum[t] = base + x - v;
    if (t == 0) g_rowstart[NN] = 2 * NE;
}

__global__ void k_offsets() {
    __shared__ int sh[1024];
    int t = threadIdx.x, n = blockIdx.x * 1024 + t;
    int v = (n < NN) ? g_deg[n] : 0;
    sh[t] = v;
    __syncthreads();
    for (int o = 1; o < 1024; o <<= 1) {
        int x = (t >= o) ? sh[t - o] : 0;
        __syncthreads();
        sh[t] += x;
        __syncthreads();
    }
    if (n < NN) g_rowstart[n] = g_blocksum[blockIdx.x] + sh[t] - v;
}

// fill CSR adjacency (both directions); forward thread also computes the
// initial softmax of the input S -> SsmA
__global__ void k_fill_sm(const int* __restrict__ ei, const float* __restrict__ S) {
    int d = blockIdx.x * blockDim.x + threadIdx.x;
    if (d >= 2 * NE) return;
    int j = (d < NE) ? d : d - NE;
    int r = ei[j], c = ei[NE + j];
    int src = (d < NE) ? r : c;
    int dst = (d < NE) ? c : r;
    int pos = g_rowstart[dst] + atomicAdd(&g_cnt[dst], 1);
    g_adj[pos] = make_float4(__int_as_float(src), __int_as_float(j),
                             g_dinv[src] * g_dinv[dst], 0.0f);
    if (d < NE) {
        float4 s = make_float4(S[j], S[NE + j], S[2 * NE + j], S[3 * NE + j]);
        float m  = fmaxf(fmaxf(s.x, s.y), fmaxf(s.z, s.w));
        float e0 = expf(s.x - m), e1 = expf(s.y - m);
        float e2 = expf(s.z - m), e3 = expf(s.w - m);
        float rr = 1.0f / (e0 + e1 + e2 + e3);
        g_SsmA[j] = make_float4(e0 * rr, e1 * rr, e2 * rr, e3 * rr);
    }
}

// conv over a batch: weights staged in smem (sw = this warp's 32 float4 as
// float*). Inner loop reads ONE scalar LDS per edge instead of 4 shuffles.
__device__ __forceinline__ void conv_batch_sm(float2& acc, const float* __restrict__ ego,
                                              int src, const float* sw,
                                              int n, int lane, int kf) {
    int j = 0;
    for (; j + 4 <= n; j += 4) {
        int s0 = __shfl_sync(FULLM, src, j);
        int s1 = __shfl_sync(FULLM, src, j + 1);
        int s2 = __shfl_sync(FULLM, src, j + 2);
        int s3 = __shfl_sync(FULLM, src, j + 3);
        float2 v0 = *reinterpret_cast<const float2*>(ego + (size_t)s0 * D + lane * 2);
        float2 v1 = *reinterpret_cast<const float2*>(ego + (size_t)s1 * D + lane * 2);
        float2 v2 = *reinterpret_cast<const float2*>(ego + (size_t)s2 * D + lane * 2);
        float2 v3 = *reinterpret_cast<const float2*>(ego + (size_t)s3 * D + lane * 2);
        float w0 = sw[(j    ) * 4 + kf];
        float w1 = sw[(j + 1) * 4 + kf];
        float w2 = sw[(j + 2) * 4 + kf];
        float w3 = sw[(j + 3) * 4 + kf];
        acc.x += w0 * v0.x; acc.y += w0 * v0.y;
        acc.x += w1 * v1.x; acc.y += w1 * v1.y;
        acc.x += w2 * v2.x; acc.y += w2 * v2.y;
        acc.x += w3 * v3.x; acc.y += w3 * v3.y;
    }
    for (; j < n; j++) {
        int sj = __shfl_sync(FULLM, src, j);
        float2 v = *reinterpret_cast<const float2*>(ego + (size_t)sj * D + lane * 2);
        float wj = sw[j * 4 + kf];
        acc.x += wj * v.x; acc.y += wj * v.y;
    }
}

// score over a batch: reduced per-factor dots are deposited to smem by the
// 8-lane group leaders (lanes 0/8/16/24); caller reads pp = sp4[lane] after
// __syncwarp(). Replaces 4 q-shuffles + divergent select per edge.
__device__ __forceinline__ void score_batch_sm(float2 acc, const float* __restrict__ tv,
                                               int item, float* sp,
                                               int n, int lane) {
    int kf = lane >> 3;
    int j = 0;
    for (; j + 2 <= n; j += 2) {
        int i0 = __shfl_sync(FULLM, item, j);
        int i1 = __shfl_sync(FULLM, item, j + 1);
        float2 t0 = *reinterpret_cast<const float2*>(tv + (size_t)i0 * D + lane * 2);
        float2 t1 = *reinterpret_cast<const float2*>(tv + (size_t)i1 * D + lane * 2);
        float pa = acc.x * t0.x + acc.y * t0.y;
        float pb = acc.x * t1.x + acc.y * t1.y;
        pa += __shfl_xor_sync(FULLM, pa, 1);  pb += __shfl_xor_sync(FULLM, pb, 1);
        pa += __shfl_xor_sync(FULLM, pa, 2);  pb += __shfl_xor_sync(FULLM, pb, 2);
        pa += __shfl_xor_sync(FULLM, pa, 4);  pb += __shfl_xor_sync(FULLM, pb, 4);
        if ((lane & 7) == 0) {
            sp[(j    ) * 4 + kf] = pa;
            sp[(j + 1) * 4 + kf] = pb;
        }
    }
    for (; j < n; j++) {
        int ij = __shfl_sync(FULLM, item, j);
        float2 t = *reinterpret_cast<const float2*>(tv + (size_t)ij * D + lane * 2);
        float p = acc.x * t.x + acc.y * t.y;
        p += __shfl_xor_sync(FULLM, p, 1);
        p += __shfl_xor_sync(FULLM, p, 2);
        p += __shfl_xor_sync(FULLM, p, 4);
        if ((lane & 7) == 0) sp[j * 4 + kf] = p;
    }
}

// ---------------- fused conv + score + softmax, one warp per node ----------------
// R14 structure + smem staging for weight broadcast (conv) and dot collection
// (score). Dead-store eliminations kept.
template <bool LASTIT, bool FINAL>
__global__ void __launch_bounds__(256)
k_fused(const float* __restrict__ ego, float* __restrict__ xn,
        const float* __restrict__ tv, float* __restrict__ tv_next,
        const float4* __restrict__ ssm_in, float4* __restrict__ ssm_out,
        float* __restrict__ outEmb) {
    __shared__ float4 s_stage[8][32];           // 4KB: per-warp staging
    int gw = (blockIdx.x * blockDim.x + threadIdx.x) >> 5;
    if (gw >= NN) return;
    int lane = threadIdx.x & 31;
    int kf = lane >> 3;
    int wslot = (threadIdx.x >> 5) & 7;
    float* sw = (float*)&s_stage[wslot][0];
    int s = g_rowstart[gw], e = g_rowstart[gw + 1];
    int deg = e - s;

    // ---- phase 1: conv ----
    float2 acc = make_float2(0.0f, 0.0f);
    int c_src = 0, c_eid = 0;
    float4 c_sm = make_float4(0, 0, 0, 0);
    for (int b = s; b < e; b += 32) {
        int n = min(32, e - b);
        int src = 0;
        if (lane < n) {
            float4 a = g_adj[b + lane];                 // coalesced batch load
            src = __float_as_int(a.x);
            float4 sm = ssm_in[__float_as_int(a.y)];    // 32 gathers in flight
            s_stage[wslot][lane] = make_float4(sm.x * a.z, sm.y * a.z,
                                               sm.z * a.z, sm.w * a.z);
            c_src = src; c_eid = __float_as_int(a.y); c_sm = sm;   // carry
        }
        __syncwarp();
        conv_batch_sm(acc, ego, src, sw, n, lane, kf);
        __syncwarp();                                   // before next overwrite
    }

    // per-factor inverse norm (every lane ends with its 8-lane group's value)
    float ss = acc.x * acc.x + acc.y * acc.y;
    ss += __shfl_xor_sync(FULLM, ss, 1);
    ss += __shfl_xor_sync(FULLM, ss, 2);
    ss += __shfl_xor_sync(FULLM, ss, 4);
    float rinv = 1.0f / fmaxf(sqrtf(ss), 1e-12f);

    if (FINAL) {
        // out = all_embs + x_new, written once, directly to d_out
        float2 av = reinterpret_cast<const float2*>(g_all + (size_t)gw * D)[lane];
        av.x += acc.x; av.y += acc.y;
        reinterpret_cast<float2*>(outEmb + (size_t)gw * D)[lane] = av;
    } else if (LASTIT) {
        reinterpret_cast<float2*>(xn + (size_t)gw * D)[lane] = acc;  // next layer's ego
        float2* ap = reinterpret_cast<float2*>(g_all + (size_t)gw * D) + lane;
        float2 av = *ap;
        av.x += acc.x; av.y += acc.y;
        *ap = av;
        float2 t;
        t.x = tanhf(acc.x * rinv);
        t.y = tanhf(acc.y * rinv);
        reinterpret_cast<float2*>(tv_next + (size_t)gw * D)[lane] = t;
    }
    // it=0: x_new never read -> no stores

    // ---- phase 2: score (user nodes only) ----
    if (gw >= NU) return;

    float r0 = __shfl_sync(FULLM, rinv, 0);
    float r1 = __shfl_sync(FULLM, rinv, 8);
    float r2 = __shfl_sync(FULLM, rinv, 16);
    float r3 = __shfl_sync(FULLM, rinv, 24);

    if (deg <= 32) {
        // reuse carried registers: c_src (=item), c_eid, c_sm (=raw ssm_in[eid])
        score_batch_sm(acc, tv, c_src, sw, deg, lane);
        __syncwarp();
        if (lane < deg) {
            float4 pp = s_stage[wslot][lane];
            float4 sv = make_float4(c_sm.x + pp.x * r0, c_sm.y + pp.y * r1,
                                    c_sm.z + pp.z * r2, c_sm.w + pp.w * r3);
            if (FINAL) {
                g_S4[c_eid] = sv;
            } else {
                float m  = fmaxf(fmaxf(sv.x, sv.y), fmaxf(sv.z, sv.w));
                float e0 = expf(sv.x - m), e1 = expf(sv.y - m);
                float e2 = expf(sv.z - m), e3 = expf(sv.w - m);
                float rr = 1.0f / (e0 + e1 + e2 + e3);
                ssm_out[c_eid] = make_float4(e0 * rr, e1 * rr, e2 * rr, e3 * rr);
            }
        }
    } else {
        for (int b = s; b < e; b += 32) {
            int n = min(32, e - b);
            int item = 0, eid = 0;
            float4 svr = make_float4(0, 0, 0, 0);
            if (lane < n) {
                float4 a = g_adj[b + lane];
                item = __float_as_int(a.x);
                eid  = __float_as_int(a.y);
                svr  = ssm_in[eid];
            }
            __syncwarp();
            score_batch_sm(acc, tv, item, sw, n, lane);
            __syncwarp();
            if (lane < n) {
                float4 pp = s_stage[wslot][lane];
                float4 sv = make_float4(svr.x + pp.x * r0, svr.y + pp.y * r1,
                                        svr.z + pp.z * r2, svr.w + pp.w * r3);
                if (FINAL) {
                    g_S4[eid] = sv;
                } else {
                    float m  = fmaxf(fmaxf(sv.x, sv.y), fmaxf(sv.z, sv.w));
                    float e0 = expf(sv.x - m), e1 = expf(sv.y - m);
                    float e2 = expf(sv.z - m), e3 = expf(sv.w - m);
                    float rr = 1.0f / (e0 + e1 + e2 + e3);
                    ssm_out[eid] = make_float4(e0 * rr, e1 * rr, e2 * rr, e3 * rr);
                }
            }
            __syncwarp();
        }
    }
}

// output S transpose [NE,4] -> [4,NE]
__global__ void k_transS_out(float* __restrict__ outS) {
    int j = blockIdx.x * blockDim.x + threadIdx.x;
    if (j >= NE) return;
    float4 s = g_S4[j];
    outS[j]          = s.x;
    outS[NE + j]     = s.y;
    outS[2 * NE + j] = s.z;
    outS[3 * NE + j] = s.w;
}

// ---------------- host orchestration ----------------

extern "C" void kernel_launch(void* const* d_in, const int* in_sizes, int n_in,
                              void* d_out, int out_size) {
    const float* user = (const float*)d_in[0];
    const float* item = (const float*)d_in[1];
    const float* Sin  = (const float*)d_in[2];
    const int*   ei   = (const int*)d_in[3];
    float* out = (float*)d_out;

    void *p_deg, *p_cnt, *p_ego0, *p_ego1, *p_tv0, *p_tv1, *p_ssmA, *p_ssmB;
    cudaGetSymbolAddress(&p_deg,  g_deg);
    cudaGetSymbolAddress(&p_cnt,  g_cnt);
    cudaGetSymbolAddress(&p_ego0, g_ego0);
    cudaGetSymbolAddress(&p_ego1, g_ego1);
    cudaGetSymbolAddress(&p_tv0,  g_tv0);
    cudaGetSymbolAddress(&p_tv1,  g_tv1);
    cudaGetSymbolAddress(&p_ssmA, g_SsmA);
    cudaGetSymbolAddress(&p_ssmB, g_SsmB);

    const int T = 256;
    const int gEdge  = (NE + T - 1) / T;
    const int gDir   = (2 * NE + T - 1) / T;
    const int gNodeW = (NN * 32 + T - 1) / T;

    // ---- setup (6 kernels + 2 memsets) ----
    cudaMemsetAsync(p_deg, 0, NN * sizeof(int), 0);
    cudaMemsetAsync(p_cnt, 0, NN * sizeof(int), 0);
    k_init_tv<<<gNodeW, T>>>(user, item);
    k_deg<<<gEdge, T>>>(ei);
    k_dinv_partial<<<NBLK, 1024>>>();
    k_scanblocks<<<1, 128>>>();
    k_offsets<<<NBLK, 1024>>>();
    k_fill_sm<<<gDir, T>>>(ei, Sin);

    // ---- 2 layers x 2 routing iterations, 1 fused kernel each ----
    float*  ego  = (float*)p_ego0;
    float*  xn   = (float*)p_ego1;
    float*  tv   = (float*)p_tv0;
    float*  tvn  = (float*)p_tv1;
    float4* ssmA = (float4*)p_ssmA;
    float4* ssmB = (float4*)p_ssmB;

    // layer 0
    k_fused<false, false><<<gNodeW, T>>>(ego, xn, tv, tvn, ssmA, ssmB, out);
    { float4* t = ssmA; ssmA = ssmB; ssmB = t; }
    k_fused<true,  false><<<gNodeW, T>>>(ego, xn, tv, tvn, ssmA, ssmB, out);
    { float4* t = ssmA; ssmA = ssmB; ssmB = t; }
    { float* t = ego; ego = xn; xn = t; t = tv; tv = tvn; tvn = t; }
    // layer 1
    k_fused<false, false><<<gNodeW, T>>>(ego, xn, tv, tvn, ssmA, ssmB, out);
    { float4* t = ssmA; ssmA = ssmB; ssmB = t; }
    k_fused<true,  true ><<<gNodeW, T>>>(ego, xn, tv, tvn, ssmA, ssmB, out);

    // ---- output S: [4, NE] after the embeddings ----
    k_transS_out<<<gEdge, T>>>(out + (size_t)NN * D);
}

// round 16
// speedup vs baseline: 1.3198x; 1.0063x over previous
#include <cuda_runtime.h>
#include <math.h>

// Problem constants (fixed by the dataset)
#define NU 60000
#define NI 40000
#define NN 100000     // NU + NI
#define NE 500000
#define D  64
#define NF 4
#define NBLK 98       // ceil(NN/1024) for the scan
#define FULLM 0xFFFFFFFFu

// ---------------- static device scratch ----------------
__device__ float  g_ego0[NN * D];
__device__ float  g_ego1[NN * D];
__device__ float  g_all [NN * D];
__device__ float  g_tv0 [NN * D];    // tv double buffer
__device__ float  g_tv1 [NN * D];
__device__ float4 g_S4  [NE];        // raw S (written only on the final iteration)
__device__ float4 g_SsmA[NE];        // softmax(S) double buffer
__device__ float4 g_SsmB[NE];
__device__ float  g_dinv[NN];
__device__ int    g_deg [NN];
__device__ int    g_rowstart[NN + 1];
__device__ int    g_cnt [NN];
__device__ int    g_blocksum[NBLK];
__device__ float4 g_adj [2 * NE];    // {src, eid, enorm, unused}

// ---------------- setup kernels (unchanged from R15) ----------------

__global__ void k_init_tv(const float* __restrict__ u, const float* __restrict__ it) {
    int gw = (blockIdx.x * blockDim.x + threadIdx.x) >> 5;
    if (gw >= NN) return;
    int lane = threadIdx.x & 31;
    const float* srcp = (gw < NU) ? (u + (size_t)gw * D)
                                  : (it + (size_t)(gw - NU) * D);
    float2 a = reinterpret_cast<const float2*>(srcp)[lane];
    reinterpret_cast<float2*>(g_ego0 + (size_t)gw * D)[lane] = a;
    reinterpret_cast<float2*>(g_all  + (size_t)gw * D)[lane] = a;
    float ss = a.x * a.x + a.y * a.y;
    ss += __shfl_xor_sync(FULLM, ss, 1);
    ss += __shfl_xor_sync(FULLM, ss, 2);
    ss += __shfl_xor_sync(FULLM, ss, 4);
    float rinv = 1.0f / fmaxf(sqrtf(ss), 1e-12f);
    float2 o;
    o.x = tanhf(a.x * rinv);
    o.y = tanhf(a.y * rinv);
    reinterpret_cast<float2*>(g_tv0 + (size_t)gw * D)[lane] = o;
}

__global__ void k_deg(const int* __restrict__ ei) {
    int j = blockIdx.x * blockDim.x + threadIdx.x;
    if (j >= NE) return;
    atomicAdd(&g_deg[ei[j]], 1);
    atomicAdd(&g_deg[ei[NE + j]], 1);
}

__global__ void k_dinv_partial() {
    __shared__ int sh[1024];
    int t = threadIdx.x, n = blockIdx.x * 1024 + t;
    int d = (n < NN) ? g_deg[n] : 0;
    if (n < NN) g_dinv[n] = (d > 0) ? (1.0f / sqrtf((float)d)) : 0.0f;
    sh[t] = d;
    __syncthreads();
    for (int o = 512; o > 0; o >>= 1) {
        if (t < o) sh[t] += sh[t + o];
        __syncthreads();
    }
    if (t == 0) g_blocksum[blockIdx.x] = sh[0];
}

__global__ void k_scanblocks() {
    __shared__ int wsum[4];
    int t = threadIdx.x;
    int v = (t < NBLK) ? g_blocksum[t] : 0;
    int x = v;
    for (int o = 1; o < 32; o <<= 1) {
        int y = __shfl_up_sync(FULLM, x, o);
        if ((t & 31) >= o) x += y;
    }
    if ((t & 31) == 31) wsum[t >> 5] = x;
    __syncthreads();
    if (t == 0) {
        int acc = 0;
        for (int i = 0; i < 4; i++) { int w = wsum[i]; wsum[i] = acc; acc += w; }
    }
    __syncthreads();
    int base = wsum[t >> 5];
    if (t < NBLK) g_blocksum[t] = base + x - v;
    if (t == 0) g_rowstart[NN] = 2 * NE;
}

__global__ void k_offsets() {
    __shared__ int sh[1024];
    int t = threadIdx.x, n = blockIdx.x * 1024 + t;
    int v = (n < NN) ? g_deg[n] : 0;
    sh[t] = v;
    __syncthreads();
    for (int o = 1; o < 1024; o <<= 1) {
        int x = (t >= o) ? sh[t - o] : 0;
        __syncthreads();
        sh[t] += x;
        __syncthreads();
    }
    if (n < NN) g_rowstart[n] = g_blocksum[blockIdx.x] + sh[t] - v;
}

__global__ void k_fill_sm(const int* __restrict__ ei, const float* __restrict__ S) {
    int d = blockIdx.x * blockDim.x + threadIdx.x;
    if (d >= 2 * NE) return;
    int j = (d < NE) ? d : d - NE;
    int r = ei[j], c = ei[NE + j];
    int src = (d < NE) ? r : c;
    int dst = (d < NE) ? c : r;
    int pos = g_rowstart[dst] + atomicAdd(&g_cnt[dst], 1);
    g_adj[pos] = make_float4(__int_as_float(src), __int_as_float(j),
                             g_dinv[src] * g_dinv[dst], 0.0f);
    if (d < NE) {
        float4 s = make_float4(S[j], S[NE + j], S[2 * NE + j], S[3 * NE + j]);
        float m  = fmaxf(fmaxf(s.x, s.y), fmaxf(s.z, s.w));
        float e0 = expf(s.x - m), e1 = expf(s.y - m);
        float e2 = expf(s.z - m), e3 = expf(s.w - m);
        float rr = 1.0f / (e0 + e1 + e2 + e3);
        g_SsmA[j] = make_float4(e0 * rr, e1 * rr, e2 * rr, e3 * rr);
    }
}

// ---------------- fused conv + score + softmax, one warp per node ----------------
// float4 lanes: a half-warp (16 lanes x 16B) covers one 256B embedding row, so
// the warp processes 2 edges per step (half = lane>>4 picks the edge).
// Smem staging (R15) extended: s_src stages source indices too -> zero per-edge
// shuffles in conv; score reduces within 4-lane quarters (2 shuffles per 2 edges).
template <bool LASTIT, bool FINAL>
__global__ void __launch_bounds__(256)
k_fused(const float* __restrict__ ego, float* __restrict__ xn,
        const float* __restrict__ tv, float* __restrict__ tv_next,
        const float4* __restrict__ ssm_in, float4* __restrict__ ssm_out,
        float* __restrict__ outEmb) {
    __shared__ float4 s_stage[8][32];           // per-warp: weights, then dots
    __shared__ int    s_src [8][32];            // per-warp: source node indices
    int gw = (blockIdx.x * blockDim.x + threadIdx.x) >> 5;
    if (gw >= NN) return;
    int lane  = threadIdx.x & 31;
    int wslot = (threadIdx.x >> 5) & 7;
    int half  = lane >> 4;                      // which of the 2 edges per step
    int q     = lane & 15;                      // float4 index within the row
    int kf2   = q >> 2;                         // factor of this lane's 4 floats
    float* sw = (float*)&s_stage[wslot][0];
    int s = g_rowstart[gw], e = g_rowstart[gw + 1];
    int deg = e - s;

    // ---- phase 1: conv ----
    float4 acc = make_float4(0.0f, 0.0f, 0.0f, 0.0f);
    int c_eid = 0;
    float4 c_sm = make_float4(0, 0, 0, 0);
    for (int b = s; b < e; b += 32) {
        int n = min(32, e - b);
        if (lane < n) {
            float4 a = g_adj[b + lane];                 // coalesced batch load
            int eid = __float_as_int(a.y);
            float4 sm = ssm_in[eid];                    // 32 gathers in flight
            s_stage[wslot][lane] = make_float4(sm.x * a.z, sm.y * a.z,
                                               sm.z * a.z, sm.w * a.z);
            s_src[wslot][lane] = __float_as_int(a.x);
            c_eid = eid; c_sm = sm;                     // carry (full list if deg<=32)
        }
        __syncwarp();
        int j = 0;
        for (; j + 4 <= n; j += 4) {                    // 4 edges per iteration
            int eA = j + half, eB = j + 2 + half;
            int sA = s_src[wslot][eA];
            int sB = s_src[wslot][eB];
            float4 vA = *reinterpret_cast<const float4*>(ego + (size_t)sA * D + q * 4);
            float4 vB = *reinterpret_cast<const float4*>(ego + (size_t)sB * D + q * 4);
            float wA = sw[eA * 4 + kf2];
            float wB = sw[eB * 4 + kf2];
            acc.x += wA * vA.x; acc.y += wA * vA.y;
            acc.z += wA * vA.z; acc.w += wA * vA.w;
            acc.x += wB * vB.x; acc.y += wB * vB.y;
            acc.z += wB * vB.z; acc.w += wB * vB.w;
        }
        for (; j < n; j += 2) {                         // 1-2 edge tail
            int eA = j + half;
            int cl = min(eA, n - 1);
            int sA = s_src[wslot][cl];
            float4 vA = *reinterpret_cast<const float4*>(ego + (size_t)sA * D + q * 4);
            float wA = (eA < n) ? sw[eA * 4 + kf2] : 0.0f;
            acc.x += wA * vA.x; acc.y += wA * vA.y;
            acc.z += wA * vA.z; acc.w += wA * vA.w;
        }
        __syncwarp();
    }
    // merge the two halves (both end with the full row afterwards)
    acc.x += __shfl_xor_sync(FULLM, acc.x, 16);
    acc.y += __shfl_xor_sync(FULLM, acc.y, 16);
    acc.z += __shfl_xor_sync(FULLM, acc.z, 16);
    acc.w += __shfl_xor_sync(FULLM, acc.w, 16);

    // per-factor inverse norm: factor kf2 spans 4 consecutive q lanes
    float ss = acc.x * acc.x + acc.y * acc.y + acc.z * acc.z + acc.w * acc.w;
    ss += __shfl_xor_sync(FULLM, ss, 1);
    ss += __shfl_xor_sync(FULLM, ss, 2);
    float rinv = 1.0f / fmaxf(sqrtf(ss), 1e-12f);

    if (FINAL) {
        if (lane < 16) {
            float4 av = *reinterpret_cast<const float4*>(g_all + (size_t)gw * D + q * 4);
            av.x += acc.x; av.y += acc.y; av.z += acc.z; av.w += acc.w;
            *reinterpret_cast<float4*>(outEmb + (size_t)gw * D + q * 4) = av;
        }
    } else if (LASTIT) {
        if (lane < 16) {
            *reinterpret_cast<float4*>(xn + (size_t)gw * D + q * 4) = acc;
            float4* ap = reinterpret_cast<float4*>(g_all + (size_t)gw * D + q * 4);
            float4 av = *ap;
            av.x += acc.x; av.y += acc.y; av.z += acc.z; av.w += acc.w;
            *ap = av;
            float4 t;
            t.x = tanhf(acc.x * rinv);
            t.y = tanhf(acc.y * rinv);
            t.z = tanhf(acc.z * rinv);
            t.w = tanhf(acc.w * rinv);
            *reinterpret_cast<float4*>(tv_next + (size_t)gw * D + q * 4) = t;
        }
    }
    // it=0: x_new never read -> no stores

    // ---- phase 2: score (user nodes only) ----
    if (gw >= NU) return;

    float r0 = __shfl_sync(FULLM, rinv, 0);
    float r1 = __shfl_sync(FULLM, rinv, 4);
    float r2 = __shfl_sync(FULLM, rinv, 8);
    float r3 = __shfl_sync(FULLM, rinv, 12);

    if (deg <= 32) {
        // s_src still holds the full list; c_eid/c_sm carried in registers
        __syncwarp();
        int j = 0;
        for (; j + 2 <= deg; j += 2) {
            int eA = j + half;
            int it = s_src[wslot][eA];
            float4 t = *reinterpret_cast<const float4*>(tv + (size_t)it * D + q * 4);
            float p = acc.x * t.x + acc.y * t.y + acc.z * t.z + acc.w * t.w;
            p += __shfl_xor_sync(FULLM, p, 1);
            p += __shfl_xor_sync(FULLM, p, 2);
            if ((lane & 3) == 0) sw[eA * 4 + kf2] = p;
        }
        if (j < deg) {
            int it = s_src[wslot][j];
            float4 t = *reinterpret_cast<const float4*>(tv + (size_t)it * D + q * 4);
            float p = acc.x * t.x + acc.y * t.y + acc.z * t.z + acc.w * t.w;
            p += __shfl_xor_sync(FULLM, p, 1);
            p += __shfl_xor_sync(FULLM, p, 2);
            if ((lane & 3) == 0 && half == 0) sw[j * 4 + kf2] = p;
        }
        __syncwarp();
        if (lane < deg) {
            float4 pp = s_stage[wslot][lane];
            float4 sv = make_float4(c_sm.x + pp.x * r0, c_sm.y + pp.y * r1,
                                    c_sm.z + pp.z * r2, c_sm.w + pp.w * r3);
            if (FINAL) {
                g_S4[c_eid] = sv;
            } else {
                float m  = fmaxf(fmaxf(sv.x, sv.y), fmaxf(sv.z, sv.w));
                float e0 = expf(sv.x - m), e1 = expf(sv.y - m);
                float e2 = expf(sv.z - m), e3 = expf(sv.w - m);
                float rr = 1.0f / (e0 + e1 + e2 + e3);
                ssm_out[c_eid] = make_float4(e0 * rr, e1 * rr, e2 * rr, e3 * rr);
            }
        }
    } else {
        for (int b = s; b < e; b += 32) {
            int n = min(32, e - b);
            int eid = 0;
            float4 svr = make_float4(0, 0, 0, 0);
            __syncwarp();
            if (lane < n) {
                float4 a = g_adj[b + lane];
                s_src[wslot][lane] = __float_as_int(a.x);
                eid = __float_as_int(a.y);
                svr = ssm_in[eid];
            }
            __syncwarp();
            int j = 0;
            for (; j + 2 <= n; j += 2) {
                int eA = j + half;
                int it = s_src[wslot][eA];
                float4 t = *reinterpret_cast<const float4*>(tv + (size_t)it * D + q * 4);
                float p = acc.x * t.x + acc.y * t.y + acc.z * t.z + acc.w * t.w;
                p += __shfl_xor_sync(FULLM, p, 1);
                p += __shfl_xor_sync(FULLM, p, 2);
                if ((lane & 3) == 0) sw[eA * 4 + kf2] = p;
            }
            if (j < n) {
                int it = s_src[wslot][j];
                float4 t = *reinterpret_cast<const float4*>(tv + (size_t)it * D + q * 4);
                float p = acc.x * t.x + acc.y * t.y + acc.z * t.z + acc.w * t.w;
                p += __shfl_xor_sync(FULLM, p, 1);
                p += __shfl_xor_sync(FULLM, p, 2);
                if ((lane & 3) == 0 && half == 0) sw[j * 4 + kf2] = p;
            }
            __syncwarp();
            if (lane < n) {
                float4 pp = s_stage[wslot][lane];
                float4 sv = make_float4(svr.x + pp.x * r0, svr.y + pp.y * r1,
                                        svr.z + pp.z * r2, svr.w + pp.w * r3);
                if (FINAL) {
                    g_S4[eid] = sv;
                } else {
                    float m  = fmaxf(fmaxf(sv.x, sv.y), fmaxf(sv.z, sv.w));
                    float e0 = expf(sv.x - m), e1 = expf(sv.y - m);
                    float e2 = expf(sv.z - m), e3 = expf(sv.w - m);
                    float rr = 1.0f / (e0 + e1 + e2 + e3);
                    ssm_out[eid] = make_float4(e0 * rr, e1 * rr, e2 * rr, e3 * rr);
                }
            }
        }
    }
}

// output S transpose [NE,4] -> [4,NE]
__global__ void k_transS_out(float* __restrict__ outS) {
    int j = blockIdx.x * blockDim.x + threadIdx.x;
    if (j >= NE) return;
    float4 s = g_S4[j];
    outS[j]          = s.x;
    outS[NE + j]     = s.y;
    outS[2 * NE + j] = s.z;
    outS[3 * NE + j] = s.w;
}

// ---------------- host orchestration ----------------

extern "C" void kernel_launch(void* const* d_in, const int* in_sizes, int n_in,
                              void* d_out, int out_size) {
    const float* user = (const float*)d_in[0];
    const float* item = (const float*)d_in[1];
    const float* Sin  = (const float*)d_in[2];
    const int*   ei   = (const int*)d_in[3];
    float* out = (float*)d_out;

    void *p_deg, *p_cnt, *p_ego0, *p_ego1, *p_tv0, *p_tv1, *p_ssmA, *p_ssmB;
    cudaGetSymbolAddress(&p_deg,  g_deg);
    cudaGetSymbolAddress(&p_cnt,  g_cnt);
    cudaGetSymbolAddress(&p_ego0, g_ego0);
    cudaGetSymbolAddress(&p_ego1, g_ego1);
    cudaGetSymbolAddress(&p_tv0,  g_tv0);
    cudaGetSymbolAddress(&p_tv1,  g_tv1);
    cudaGetSymbolAddress(&p_ssmA, g_SsmA);
    cudaGetSymbolAddress(&p_ssmB, g_SsmB);

    const int T = 256;
    const int gEdge  = (NE + T - 1) / T;
    const int gDir   = (2 * NE + T - 1) / T;
    const int gNodeW = (NN * 32 + T - 1) / T;

    // ---- setup (6 kernels + 2 memsets) ----
    cudaMemsetAsync(p_deg, 0, NN * sizeof(int), 0);
    cudaMemsetAsync(p_cnt, 0, NN * sizeof(int), 0);
    k_init_tv<<<gNodeW, T>>>(user, item);
    k_deg<<<gEdge, T>>>(ei);
    k_dinv_partial<<<NBLK, 1024>>>();
    k_scanblocks<<<1, 128>>>();
    k_offsets<<<NBLK, 1024>>>();
    k_fill_sm<<<gDir, T>>>(ei, Sin);

    // ---- 2 layers x 2 routing iterations, 1 fused kernel each ----
    float*  ego  = (float*)p_ego0;
    float*  xn   = (float*)p_ego1;
    float*  tv   = (float*)p_tv0;
    float*  tvn  = (float*)p_tv1;
    float4* ssmA = (float4*)p_ssmA;
    float4* ssmB = (float4*)p_ssmB;

    // layer 0
    k_fused<false, false><<<gNodeW, T>>>(ego, xn, tv, tvn, ssmA, ssmB, out);
    { float4* t = ssmA; ssmA = ssmB; ssmB = t; }
    k_fused<true,  false><<<gNodeW, T>>>(ego, xn, tv, tvn, ssmA, ssmB, out);
    { float4* t = ssmA; ssmA = ssmB; ssmB = t; }
    { float* t = ego; ego = xn; xn = t; t = tv; tv = tvn; tvn = t; }
    // layer 1
    k_fused<false, false><<<gNodeW, T>>>(ego, xn, tv, tvn, ssmA, ssmB, out);
    { float4* t = ssmA; ssmA = ssmB; ssmB = t; }
    k_fused<true,  true ><<<gNodeW, T>>>(ego, xn, tv, tvn, ssmA, ssmB, out);

    // ---- output S: [4, NE] after the embeddings ----
    k_transS_out<<<gEdge, T>>>(out + (size_t)NN * D);
}

// round 17
// speedup vs baseline: 1.5257x; 1.1560x over previous
#include <cuda_runtime.h>
#include <math.h>

// Problem constants (fixed by the dataset)
#define NU 60000
#define NI 40000
#define NN 100000     // NU + NI (even; NU even -> node pairs never straddle)
#define NE 500000
#define D  64
#define NF 4
#define NBLK 98
#define FULLM 0xFFFFFFFFu

// ---------------- static device scratch ----------------
__device__ float  g_ego0[NN * D];
__device__ float  g_ego1[NN * D];
__device__ float  g_all [NN * D];
__device__ float  g_tv0 [NN * D];
__device__ float  g_tv1 [NN * D];
__device__ float4 g_S4  [NE];
__device__ float4 g_SsmA[NE];
__device__ float4 g_SsmB[NE];
__device__ float  g_dinv[NN];
__device__ int    g_deg [NN];
__device__ int    g_rowstart[NN + 1];
__device__ int    g_cnt [NN];
__device__ int    g_blocksum[NBLK];
__device__ float4 g_adj [2 * NE];    // {src, eid, enorm, unused}

// ---------------- setup kernels (unchanged) ----------------

__global__ void k_init_tv(const float* __restrict__ u, const float* __restrict__ it) {
    int gw = (blockIdx.x * blockDim.x + threadIdx.x) >> 5;
    if (gw >= NN) return;
    int lane = threadIdx.x & 31;
    const float* srcp = (gw < NU) ? (u + (size_t)gw * D)
                                  : (it + (size_t)(gw - NU) * D);
    float2 a = reinterpret_cast<const float2*>(srcp)[lane];
    reinterpret_cast<float2*>(g_ego0 + (size_t)gw * D)[lane] = a;
    reinterpret_cast<float2*>(g_all  + (size_t)gw * D)[lane] = a;
    float ss = a.x * a.x + a.y * a.y;
    ss += __shfl_xor_sync(FULLM, ss, 1);
    ss += __shfl_xor_sync(FULLM, ss, 2);
    ss += __shfl_xor_sync(FULLM, ss, 4);
    float rinv = 1.0f / fmaxf(sqrtf(ss), 1e-12f);
    float2 o;
    o.x = tanhf(a.x * rinv);
    o.y = tanhf(a.y * rinv);
    reinterpret_cast<float2*>(g_tv0 + (size_t)gw * D)[lane] = o;
}

__global__ void k_deg(const int* __restrict__ ei) {
    int j = blockIdx.x * blockDim.x + threadIdx.x;
    if (j >= NE) return;
    atomicAdd(&g_deg[ei[j]], 1);
    atomicAdd(&g_deg[ei[NE + j]], 1);
}

__global__ void k_dinv_partial() {
    __shared__ int sh[1024];
    int t = threadIdx.x, n = blockIdx.x * 1024 + t;
    int d = (n < NN) ? g_deg[n] : 0;
    if (n < NN) g_dinv[n] = (d > 0) ? (1.0f / sqrtf((float)d)) : 0.0f;
    sh[t] = d;
    __syncthreads();
    for (int o = 512; o > 0; o >>= 1) {
        if (t < o) sh[t] += sh[t + o];
        __syncthreads();
    }
    if (t == 0) g_blocksum[blockIdx.x] = sh[0];
}

__global__ void k_scanblocks() {
    __shared__ int wsum[4];
    int t = threadIdx.x;
    int v = (t < NBLK) ? g_blocksum[t] : 0;
    int x = v;
    for (int o = 1; o < 32; o <<= 1) {
        int y = __shfl_up_sync(FULLM, x, o);
        if ((t & 31) >= o) x += y;
    }
    if ((t & 31) == 31) wsum[t >> 5] = x;
    __syncthreads();
    if (t == 0) {
        int acc = 0;
        for (int i = 0; i < 4; i++) { int w = wsum[i]; wsum[i] = acc; acc += w; }
    }
    __syncthreads();
    int base = wsum[t >> 5];
    if (t < NBLK) g_blocksum[t] = base + x - v;
    if (t == 0) g_rowstart[NN] = 2 * NE;
}

__global__ void k_offsets() {
    __shared__ int sh[1024];
    int t = threadIdx.x, n = blockIdx.x * 1024 + t;
    int v = (n < NN) ? g_deg[n] : 0;
    sh[t] = v;
    __syncthreads();
    for (int o = 1; o < 1024; o <<= 1) {
        int x = (t >= o) ? sh[t - o] : 0;
        __syncthreads();
        sh[t] += x;
        __syncthreads();
    }
    if (n < NN) g_rowstart[n] = g_blocksum[blockIdx.x] + sh[t] - v;
}

__global__ void k_fill_sm(const int* __restrict__ ei, const float* __restrict__ S) {
    int d = blockIdx.x * blockDim.x + threadIdx.x;
    if (d >= 2 * NE) return;
    int j = (d < NE) ? d : d - NE;
    int r = ei[j], c = ei[NE + j];
    int src = (d < NE) ? r : c;
    int dst = (d < NE) ? c : r;
    int pos = g_rowstart[dst] + atomicAdd(&g_cnt[dst], 1);
    g_adj[pos] = make_float4(__int_as_float(src), __int_as_float(j),
                             g_dinv[src] * g_dinv[dst], 0.0f);
    if (d < NE) {
        float4 s = make_float4(S[j], S[NE + j], S[2 * NE + j], S[3 * NE + j]);
        float m  = fmaxf(fmaxf(s.x, s.y), fmaxf(s.z, s.w));
        float e0 = expf(s.x - m), e1 = expf(s.y - m);
        float e2 = expf(s.z - m), e3 = expf(s.w - m);
        float rr = 1.0f / (e0 + e1 + e2 + e3);
        g_SsmA[j] = make_float4(e0 * rr, e1 * rr, e2 * rr, e3 * rr);
    }
}

// ---------------- hot-loop helpers ----------------
// 2 edges per warp-step: half = lane>>4 picks the edge, q = lane&15 the float4.

__device__ __forceinline__ void conv_span(float4& acc, const float* __restrict__ ego,
                                          const int* ssrc, const float* sw,
                                          int lo, int hi, int half, int q, int kf2) {
    int j = lo;
    for (; j + 2 <= hi; j += 2) {
        int eA = j + half;
        int sA = ssrc[eA];
        float4 v = *reinterpret_cast<const float4*>(ego + (size_t)sA * D + q * 4);
        float w = sw[eA * 4 + kf2];
        acc.x += w * v.x; acc.y += w * v.y;
        acc.z += w * v.z; acc.w += w * v.w;
    }
    if (j < hi) {
        int sA = ssrc[j];
        float4 v = *reinterpret_cast<const float4*>(ego + (size_t)sA * D + q * 4);
        float w = (half == 0) ? sw[j * 4 + kf2] : 0.0f;
        acc.x += w * v.x; acc.y += w * v.y;
        acc.z += w * v.z; acc.w += w * v.w;
    }
}

// dots for edges [lo,hi); edge e uses acc0 if e<d0 else acc1; deposits to sw
__device__ __forceinline__ void score_span(float4 a0, float4 a1, int d0,
                                           const float* __restrict__ tv,
                                           const int* ssrc, float* sw,
                                           int lo, int hi, int half, int q,
                                           int kf2, int lane) {
    int j = lo;
    for (; j + 2 <= hi; j += 2) {
        int eA = j + half;
        int it = ssrc[eA];
        float4 t = *reinterpret_cast<const float4*>(tv + (size_t)it * D + q * 4);
        float4 a = (eA < d0) ? a0 : a1;
        float p = a.x * t.x + a.y * t.y + a.z * t.z + a.w * t.w;
        p += __shfl_xor_sync(FULLM, p, 1);
        p += __shfl_xor_sync(FULLM, p, 2);
        if ((lane & 3) == 0) sw[eA * 4 + kf2] = p;
    }
    if (j < hi) {
        int it = ssrc[j];
        float4 t = *reinterpret_cast<const float4*>(tv + (size_t)it * D + q * 4);
        float4 a = (j < d0) ? a0 : a1;
        float p = a.x * t.x + a.y * t.y + a.z * t.z + a.w * t.w;
        p += __shfl_xor_sync(FULLM, p, 1);
        p += __shfl_xor_sync(FULLM, p, 2);
        if ((lane & 3) == 0 && half == 0) sw[j * 4 + kf2] = p;
    }
}

// ---------------- fused conv + score + softmax, one warp per NODE PAIR ----------
template <bool LASTIT, bool FINAL>
__global__ void __launch_bounds__(256)
k_fused(const float* __restrict__ ego, float* __restrict__ xn,
        const float* __restrict__ tv, float* __restrict__ tv_next,
        const float4* __restrict__ ssm_in, float4* __restrict__ ssm_out,
        float* __restrict__ outEmb) {
    __shared__ float4 s_stage[8][32];           // per-warp: weights, then dots
    __shared__ int    s_src [8][32];            // per-warp: source node indices
    int gp = (blockIdx.x * blockDim.x + threadIdx.x) >> 5;   // pair index
    int n0 = 2 * gp;
    if (n0 >= NN) return;
    int lane  = threadIdx.x & 31;
    int wslot = (threadIdx.x >> 5) & 7;
    int half  = lane >> 4;
    int q     = lane & 15;
    int kf2   = q >> 2;
    float* sw = (float*)&s_stage[wslot][0];
    int* ssrc = &s_src[wslot][0];

    // contiguous pair ranges: [s0,e0) and [e0,e1)
    int rsv = (lane < 3) ? g_rowstart[n0 + lane] : 0;
    int s0 = __shfl_sync(FULLM, rsv, 0);
    int e0 = __shfl_sync(FULLM, rsv, 1);
    int e1 = __shfl_sync(FULLM, rsv, 2);
    int d0 = e0 - s0;
    int dt = e1 - s0;                            // combined degree
    bool fast = (dt <= 32);

    // ---- phase 1: conv for both nodes ----
    float4 acc0 = make_float4(0, 0, 0, 0);
    float4 acc1 = make_float4(0, 0, 0, 0);
    int c_eid = 0;
    float4 c_sm = make_float4(0, 0, 0, 0);

    if (fast) {
        if (lane < dt) {
            float4 a = g_adj[s0 + lane];             // ONE coalesced batch for pair
            c_eid = __float_as_int(a.y);
            c_sm  = ssm_in[c_eid];                   // 32 gathers in flight
            s_stage[wslot][lane] = make_float4(c_sm.x * a.z, c_sm.y * a.z,
                                               c_sm.z * a.z, c_sm.w * a.z);
            ssrc[lane] = __float_as_int(a.x);
        }
        __syncwarp();
        conv_span(acc0, ego, ssrc, sw, 0,  d0, half, q, kf2);
        conv_span(acc1, ego, ssrc, sw, d0, dt, half, q, kf2);
        // NOTE: keep stage/src intact for phase 2
    } else {
        // slow path: per node, R16-style batches
        int ses[2][2] = {{s0, e0}, {e0, e1}};
        for (int nd = 0; nd < 2; nd++) {
            float4* accp = nd ? &acc1 : &acc0;
            for (int b = ses[nd][0]; b < ses[nd][1]; b += 32) {
                int n = min(32, ses[nd][1] - b);
                if (lane < n) {
                    float4 a = g_adj[b + lane];
                    float4 sm = ssm_in[__float_as_int(a.y)];
                    s_stage[wslot][lane] = make_float4(sm.x * a.z, sm.y * a.z,
                                                       sm.z * a.z, sm.w * a.z);
                    ssrc[lane] = __float_as_int(a.x);
                }
                __syncwarp();
                conv_span(*accp, ego, ssrc, sw, 0, n, half, q, kf2);
                __syncwarp();
            }
        }
    }

    // merge halves (all lanes end with the complete rows)
    acc0.x += __shfl_xor_sync(FULLM, acc0.x, 16);
    acc0.y += __shfl_xor_sync(FULLM, acc0.y, 16);
    acc0.z += __shfl_xor_sync(FULLM, acc0.z, 16);
    acc0.w += __shfl_xor_sync(FULLM, acc0.w, 16);
    acc1.x += __shfl_xor_sync(FULLM, acc1.x, 16);
    acc1.y += __shfl_xor_sync(FULLM, acc1.y, 16);
    acc1.z += __shfl_xor_sync(FULLM, acc1.z, 16);
    acc1.w += __shfl_xor_sync(FULLM, acc1.w, 16);

    // per-factor inverse norms (lane's kf2 group)
    float ss0 = acc0.x * acc0.x + acc0.y * acc0.y + acc0.z * acc0.z + acc0.w * acc0.w;
    ss0 += __shfl_xor_sync(FULLM, ss0, 1);
    ss0 += __shfl_xor_sync(FULLM, ss0, 2);
    float rinv0 = 1.0f / fmaxf(sqrtf(ss0), 1e-12f);
    float ss1 = acc1.x * acc1.x + acc1.y * acc1.y + acc1.z * acc1.z + acc1.w * acc1.w;
    ss1 += __shfl_xor_sync(FULLM, ss1, 1);
    ss1 += __shfl_xor_sync(FULLM, ss1, 2);
    float rinv1 = 1.0f / fmaxf(sqrtf(ss1), 1e-12f);

    // epilogues: half 0 lanes write node n0, half 1 lanes write node n0+1
    {
        int node = n0 + half;
        float4 a = half ? acc1 : acc0;
        float rv = half ? rinv1 : rinv0;
        if (FINAL) {
            float4 av = *reinterpret_cast<const float4*>(g_all + (size_t)node * D + q * 4);
            av.x += a.x; av.y += a.y; av.z += a.z; av.w += a.w;
            *reinterpret_cast<float4*>(outEmb + (size_t)node * D + q * 4) = av;
        } else if (LASTIT) {
            *reinterpret_cast<float4*>(xn + (size_t)node * D + q * 4) = a;
            float4* ap = reinterpret_cast<float4*>(g_all + (size_t)node * D + q * 4);
            float4 av = *ap;
            av.x += a.x; av.y += a.y; av.z += a.z; av.w += a.w;
            *ap = av;
            float4 t;
            t.x = tanhf(a.x * rv);
            t.y = tanhf(a.y * rv);
            t.z = tanhf(a.z * rv);
            t.w = tanhf(a.w * rv);
            *reinterpret_cast<float4*>(tv_next + (size_t)node * D + q * 4) = t;
        }
    }
    // it=0: x_new never read -> no stores

    // ---- phase 2: score (user pairs only; NU even -> pair is all-user or all-item)
    if (n0 >= NU) return;

    // per-node rinv vectors (factor f at shfl lane 4*f)
    float4 rr0 = make_float4(__shfl_sync(FULLM, rinv0, 0),  __shfl_sync(FULLM, rinv0, 4),
                             __shfl_sync(FULLM, rinv0, 8),  __shfl_sync(FULLM, rinv0, 12));
    float4 rr1 = make_float4(__shfl_sync(FULLM, rinv1, 0),  __shfl_sync(FULLM, rinv1, 4),
                             __shfl_sync(FULLM, rinv1, 8),  __shfl_sync(FULLM, rinv1, 12));

    if (fast) {
        __syncwarp();                                // conv reads done before overwrite
        score_span(acc0, acc1, d0, tv, ssrc, sw, 0, dt, half, q, kf2, lane);
        __syncwarp();
        if (lane < dt) {
            float4 rr = (lane < d0) ? rr0 : rr1;
            float4 pp = s_stage[wslot][lane];
            float4 sv = make_float4(c_sm.x + pp.x * rr.x, c_sm.y + pp.y * rr.y,
                                    c_sm.z + pp.z * rr.z, c_sm.w + pp.w * rr.w);
            if (FINAL) {
                g_S4[c_eid] = sv;
            } else {
                float m  = fmaxf(fmaxf(sv.x, sv.y), fmaxf(sv.z, sv.w));
                float e0 = expf(sv.x - m), e1v = expf(sv.y - m);
                float e2 = expf(sv.z - m), e3 = expf(sv.w - m);
                float rrs = 1.0f / (e0 + e1v + e2 + e3);
                ssm_out[c_eid] = make_float4(e0 * rrs, e1v * rrs, e2 * rrs, e3 * rrs);
            }
        }
    } else {
        int ses[2][2] = {{s0, e0}, {e0, e1}};
        for (int nd = 0; nd < 2; nd++) {
            float4 an = nd ? acc1 : acc0;
            float4 rr = nd ? rr1 : rr0;
            for (int b = ses[nd][0]; b < ses[nd][1]; b += 32) {
                int n = min(32, ses[nd][1] - b);
                int eid = 0;
                float4 svr = make_float4(0, 0, 0, 0);
                __syncwarp();
                if (lane < n) {
                    float4 a = g_adj[b + lane];
                    ssrc[lane] = __float_as_int(a.x);
                    eid = __float_as_int(a.y);
                    svr = ssm_in[eid];
                }
                __syncwarp();
                score_span(an, an, n, tv, ssrc, sw, 0, n, half, q, kf2, lane);
                __syncwarp();
                if (lane < n) {
                    float4 pp = s_stage[wslot][lane];
                    float4 sv = make_float4(svr.x + pp.x * rr.x, svr.y + pp.y * rr.y,
                                            svr.z + pp.z * rr.z, svr.w + pp.w * rr.w);
                    if (FINAL) {
                        g_S4[eid] = sv;
                    } else {
                        float m  = fmaxf(fmaxf(sv.x, sv.y), fmaxf(sv.z, sv.w));
                        float e0 = expf(sv.x - m), e1v = expf(sv.y - m);
                        float e2 = expf(sv.z - m), e3 = expf(sv.w - m);
                        float rrs = 1.0f / (e0 + e1v + e2 + e3);
                        ssm_out[eid] = make_float4(e0 * rrs, e1v * rrs, e2 * rrs, e3 * rrs);
                    }
                }
            }
        }
    }
}

// output S transpose [NE,4] -> [4,NE]
__global__ void k_transS_out(float* __restrict__ outS) {
    int j = blockIdx.x * blockDim.x + threadIdx.x;
    if (j >= NE) return;
    float4 s = g_S4[j];
    outS[j]          = s.x;
    outS[NE + j]     = s.y;
    outS[2 * NE + j] = s.z;
    outS[3 * NE + j] = s.w;
}

// ---------------- host orchestration ----------------

extern "C" void kernel_launch(void* const* d_in, const int* in_sizes, int n_in,
                              void* d_out, int out_size) {
    const float* user = (const float*)d_in[0];
    const float* item = (const float*)d_in[1];
    const float* Sin  = (const float*)d_in[2];
    const int*   ei   = (const int*)d_in[3];
    float* out = (float*)d_out;

    void *p_deg, *p_cnt, *p_ego0, *p_ego1, *p_tv0, *p_tv1, *p_ssmA, *p_ssmB;
    cudaGetSymbolAddress(&p_deg,  g_deg);
    cudaGetSymbolAddress(&p_cnt,  g_cnt);
    cudaGetSymbolAddress(&p_ego0, g_ego0);
    cudaGetSymbolAddress(&p_ego1, g_ego1);
    cudaGetSymbolAddress(&p_tv0,  g_tv0);
    cudaGetSymbolAddress(&p_tv1,  g_tv1);
    cudaGetSymbolAddress(&p_ssmA, g_SsmA);
    cudaGetSymbolAddress(&p_ssmB, g_SsmB);

    const int T = 256;
    const int gEdge  = (NE + T - 1) / T;
    const int gDir   = (2 * NE + T - 1) / T;
    const int gNodeW = (NN * 32 + T - 1) / T;
    const int gPairW = ((NN / 2) * 32 + T - 1) / T;

    // ---- setup ----
    cudaMemsetAsync(p_deg, 0, NN * sizeof(int), 0);
    cudaMemsetAsync(p_cnt, 0, NN * sizeof(int), 0);
    k_init_tv<<<gNodeW, T>>>(user, item);
    k_deg<<<gEdge, T>>>(ei);
    k_dinv_partial<<<NBLK, 1024>>>();
    k_scanblocks<<<1, 128>>>();
    k_offsets<<<NBLK, 1024>>>();
    k_fill_sm<<<gDir, T>>>(ei, Sin);

    // ---- 2 layers x 2 routing iterations, 1 fused kernel each ----
    float*  ego  = (float*)p_ego0;
    float*  xn   = (float*)p_ego1;
    float*  tv   = (float*)p_tv0;
    float*  tvn  = (float*)p_tv1;
    float4* ssmA = (float4*)p_ssmA;
    float4* ssmB = (float4*)p_ssmB;

    // layer 0
    k_fused<false, false><<<gPairW, T>>>(ego, xn, tv, tvn, ssmA, ssmB, out);
    { float4* t = ssmA; ssmA = ssmB; ssmB = t; }
    k_fused<true,  false><<<gPairW, T>>>(ego, xn, tv, tvn, ssmA, ssmB, out);
    { float4* t = ssmA; ssmA = ssmB; ssmB = t; }
    { float* t = ego; ego = xn; xn = t; t = tv; tv = tvn; tvn = t; }
    // layer 1
    k_fused<false, false><<<gPairW, T>>>(ego, xn, tv, tvn, ssmA, ssmB, out);
    { float4* t = ssmA; ssmA = ssmB; ssmB = t; }
    k_fused<true,  true ><<<gPairW, T>>>(ego, xn, tv, tvn, ssmA, ssmB, out);

    // ---- output S: [4, NE] after the embeddings ----
    k_transS_out<<<gEdge, T>>>(out + (size_t)NN * D);
}